// round 14
// baseline (speedup 1.0000x reference)
#include <cuda_runtime.h>
#include <cuda_bf16.h>
#include <cstdint>

#define NN 6144
#define IN_DIM 512
#define CHANNELS 4
#define C_DIM 64
#define FDIM 256          // CHANNELS * C_DIM
#define CAP 128           // max neighbors per row (mean ~31, sd ~5.5)

// -------- scratch (device globals; no allocation allowed) --------
// Rows of g_feats are stored PERMUTED: canonical element e (owner lane
// l = e>>3, sub s = e&7) lives at float offset (s>=4)*128 + l*4 + (s&3).
// Dense per-lane 16B neighbor loads + 8-lane channel groups (5-shfl softmax).
// Row NN is a permanent all-zero row (sentinel target).
__device__ float g_featsA[(size_t)(NN + 1) * FDIM];
__device__ float g_featsB[(size_t)(NN + 1) * FDIM];
__device__ int   g_ell[(size_t)NN * CAP + 64];
__device__ int   g_deg[NN];

#define FMA2(d, a, b, c) \
    asm("fma.rn.f32x2 %0, %1, %2, %3;" : "=l"(d) : "l"(a), "l"(b), "l"(c))
#define PACK2(d, x) \
    asm("mov.b64 %0, {%1, %2};" : "=l"(d) : "f"(x), "f"(x))
#define UNPACK2(lo, hi, s) \
    asm("mov.b64 {%0, %1}, %2;" : "=f"(lo), "=f"(hi) : "l"(s))

// forced (non-CSE-able) 16B global load
__device__ __forceinline__ float4 ld128_force(const float* p) {
    float4 v;
    asm volatile("ld.global.nc.v4.f32 {%0, %1, %2, %3}, [%4];"
                 : "=f"(v.x), "=f"(v.y), "=f"(v.z), "=f"(v.w) : "l"(p));
    return v;
}

// ============================================================
// Kernel 1: dense adj -> ELL (order-preserving, deterministic)
// warp/row, int4 + 4-ballot compaction, sentinel padding to x4.
// ============================================================
__global__ __launch_bounds__(256) void build_ell_kernel(const int* __restrict__ adj) {
    int row = blockIdx.x * 8 + (threadIdx.x >> 5);
    int lane = threadIdx.x & 31;
    const int4* arow = (const int4*)(adj + (size_t)row * NN);
    unsigned lt = (1u << lane) - 1u;
    int total = 0;
    int* erow = g_ell + (size_t)row * CAP;
    for (int it = 0; it < NN / 128; it++) {
        int4 v = arow[it * 32 + lane];
        bool p0 = v.x > 0, p1 = v.y > 0, p2 = v.z > 0, p3 = v.w > 0;
        unsigned b0 = __ballot_sync(0xffffffffu, p0);
        unsigned b1 = __ballot_sync(0xffffffffu, p1);
        unsigned b2 = __ballot_sync(0xffffffffu, p2);
        unsigned b3 = __ballot_sync(0xffffffffu, p3);
        int basec = __popc(b0 & lt) + __popc(b1 & lt) + __popc(b2 & lt) + __popc(b3 & lt);
        int idx0 = it * 128 + lane * 4;
        int pos = total + basec;
        if (p0) { if (pos < CAP) erow[pos] = idx0; pos++; }
        if (p1) { if (pos < CAP) erow[pos] = idx0 + 1; pos++; }
        if (p2) { if (pos < CAP) erow[pos] = idx0 + 2; pos++; }
        if (p3) { if (pos < CAP) erow[pos] = idx0 + 3; }
        total += __popc(b0) + __popc(b1) + __popc(b2) + __popc(b3);
    }
    int tc = total < CAP ? total : CAP;
    int pad = (tc + 3) & ~3;
    if (lane < pad - tc) erow[tc + lane] = NN;   // sentinel -> zero row
    if (lane == 0) g_deg[row] = pad;
}

// ============================================================
// Kernel 2: feats0 = l2norm(features @ W + b) -> permuted layout.
// R13 version: 64x64 tile, 256 threads, BK=16, packed f32x2,
// double-buffered smem (one barrier per chunk).
// ============================================================
__global__ __launch_bounds__(256) void project_kernel(const float* __restrict__ feat,
                                                      const float* __restrict__ W,
                                                      const float* __restrict__ bias) {
    __shared__ float sA[2][16][64];
    __shared__ float sB[2][16][64];
    __shared__ float s_scale[64];

    const int c  = blockIdx.y;
    const int n0 = blockIdx.x * 64;
    const int t  = threadIdx.x;
    const int tx = t & 15, ty = t >> 4;

    unsigned long long acc2[2][4];
#pragma unroll
    for (int i = 0; i < 2; i++)
#pragma unroll
        for (int j = 0; j < 4; j++) acc2[i][j] = 0ull;

    const float* Wc = W + (size_t)c * IN_DIM * C_DIM;
    const int lrow = t >> 2, lseg = t & 3;
    const int ld   = t >> 4, lks  = t & 15;

    {
        float4 a = *(const float4*)(feat + (size_t)(n0 + lrow) * IN_DIM + lseg * 4);
        sA[0][lseg * 4 + 0][lrow] = a.x;
        sA[0][lseg * 4 + 1][lrow] = a.y;
        sA[0][lseg * 4 + 2][lrow] = a.z;
        sA[0][lseg * 4 + 3][lrow] = a.w;
        float4 bv = *(const float4*)(Wc + (size_t)ld * C_DIM + lks * 4);
        *(float4*)&sB[0][ld][lks * 4] = bv;
    }
    __syncthreads();

    int cur = 0;
    for (int d0 = 0; d0 < IN_DIM; d0 += 16) {
        float4 an, bn;
        const bool hasNext = (d0 + 16 < IN_DIM);
        if (hasNext) {
            an = *(const float4*)(feat + (size_t)(n0 + lrow) * IN_DIM + d0 + 16 + lseg * 4);
            bn = *(const float4*)(Wc + (size_t)(d0 + 16 + ld) * C_DIM + lks * 4);
        }
#pragma unroll
        for (int d = 0; d < 16; d++) {
            unsigned long long ap0 = *(const unsigned long long*)&sA[cur][d][ty * 4];
            unsigned long long ap1 = *(const unsigned long long*)&sA[cur][d][ty * 4 + 2];
            float4 bv2 = *(const float4*)&sB[cur][d][tx * 4];
            unsigned long long bp0, bp1, bp2, bp3;
            PACK2(bp0, bv2.x); PACK2(bp1, bv2.y); PACK2(bp2, bv2.z); PACK2(bp3, bv2.w);
            FMA2(acc2[0][0], ap0, bp0, acc2[0][0]);
            FMA2(acc2[0][1], ap0, bp1, acc2[0][1]);
            FMA2(acc2[0][2], ap0, bp2, acc2[0][2]);
            FMA2(acc2[0][3], ap0, bp3, acc2[0][3]);
            FMA2(acc2[1][0], ap1, bp0, acc2[1][0]);
            FMA2(acc2[1][1], ap1, bp1, acc2[1][1]);
            FMA2(acc2[1][2], ap1, bp2, acc2[1][2]);
            FMA2(acc2[1][3], ap1, bp3, acc2[1][3]);
        }
        if (hasNext) {
            int nxt = cur ^ 1;
            sA[nxt][lseg * 4 + 0][lrow] = an.x;
            sA[nxt][lseg * 4 + 1][lrow] = an.y;
            sA[nxt][lseg * 4 + 2][lrow] = an.z;
            sA[nxt][lseg * 4 + 3][lrow] = an.w;
            *(float4*)&sB[nxt][ld][lks * 4] = bn;
        }
        __syncthreads();
        cur ^= 1;
    }

    float r[4][4];
#pragma unroll
    for (int i = 0; i < 2; i++)
#pragma unroll
        for (int j = 0; j < 4; j++)
            UNPACK2(r[2 * i][j], r[2 * i + 1][j], acc2[i][j]);

    float4 bb4 = *(const float4*)(bias + c * C_DIM + tx * 4);
    float bb[4] = {bb4.x, bb4.y, bb4.z, bb4.w};
    float ss[4];
#pragma unroll
    for (int i = 0; i < 4; i++) {
        float s = 0.f;
#pragma unroll
        for (int j = 0; j < 4; j++) {
            r[i][j] += bb[j];
            s += r[i][j] * r[i][j];
        }
        ss[i] = s;
    }
#pragma unroll
    for (int off = 1; off < 16; off <<= 1)
#pragma unroll
        for (int i = 0; i < 4; i++) ss[i] += __shfl_xor_sync(0xffffffffu, ss[i], off);
    if (tx == 0) {
#pragma unroll
        for (int i = 0; i < 4; i++) s_scale[ty * 4 + i] = rsqrtf(fmaxf(ss[i], 1e-24f));
    }
    __syncthreads();
    const int ppos = (tx & 1) * 128 + (c * 8 + (tx >> 1)) * 4;
#pragma unroll
    for (int i = 0; i < 4; i++) {
        float s = s_scale[ty * 4 + i];
        float4 o = make_float4(r[i][0] * s, r[i][1] * s, r[i][2] * s, r[i][3] * s);
        *(float4*)(g_featsA + (size_t)(n0 + ty * 4 + i) * FDIM + ppos) = o;
    }
}

// ============================================================
// Kernel 3: one iteration, y-RELOAD variant. Phase 1 loads y,
// computes p, lets y die; after the 5-shfl softmax chain, phase 2
// force-reloads y (asm volatile, L1-hit) and accumulates. Live set
// shrinks ~32 regs -> fits 64-reg cap WITHOUT spills -> 8 blocks/SM.
// ============================================================
__global__ __launch_bounds__(128, 8) void iterate_kernel(int pass, float* __restrict__ d_final) {
    const float* __restrict__ src = (pass == 1) ? g_featsB : g_featsA;
    float* __restrict__ dst = (pass == 0) ? g_featsB : (pass == 1) ? g_featsA : d_final;

    const int w = threadIdx.x >> 5, lane = threadIdx.x & 31;
    const int n = blockIdx.x * 4 + w;

    const float* xrow = src + (size_t)n * FDIM + lane * 4;
    float4 x0 = *(const float4*)xrow;          // canonical [8l, 8l+4)
    float4 x1 = *(const float4*)(xrow + 128);  // canonical [8l+4, 8l+8)
    float4 a0 = make_float4(0.f, 0.f, 0.f, 0.f);
    float4 a1 = make_float4(0.f, 0.f, 0.f, 0.f);

    const int dp = g_deg[n];                 // padded to multiple of 4
    const int* erow = g_ell + (size_t)n * CAP;

    for (int i = 0; i < dp; i += 4) {
        const float* yp[4];
#pragma unroll
        for (int j = 0; j < 4; j++)
            yp[j] = src + (size_t)__ldg(erow + i + j) * FDIM + lane * 4;

        // phase 1: load y, compute channel dots (y dies here)
        float p[4];
#pragma unroll
        for (int j = 0; j < 4; j++) {
            float4 y0 = *(const float4*)yp[j];
            float4 y1 = *(const float4*)(yp[j] + 128);
            p[j] = x0.x * y0.x + x0.y * y0.y + x0.z * y0.z + x0.w * y0.w +
                   x1.x * y1.x + x1.y * y1.y + x1.z * y1.z + x1.w * y1.w;
        }
#pragma unroll
        for (int j = 0; j < 4; j++) p[j] += __shfl_xor_sync(0xffffffffu, p[j], 1);
#pragma unroll
        for (int j = 0; j < 4; j++) p[j] += __shfl_xor_sync(0xffffffffu, p[j], 2);
#pragma unroll
        for (int j = 0; j < 4; j++) p[j] += __shfl_xor_sync(0xffffffffu, p[j], 4);
        // |p| <= 1 (unit-norm channel rows): no max-shift needed
        float e[4], t[4];
#pragma unroll
        for (int j = 0; j < 4; j++) e[j] = __expf(p[j]);
#pragma unroll
        for (int j = 0; j < 4; j++) t[j] = e[j] + __shfl_xor_sync(0xffffffffu, e[j], 8);
#pragma unroll
        for (int j = 0; j < 4; j++) t[j] += __shfl_xor_sync(0xffffffffu, t[j], 16);

        // phase 2: forced reload (L1 hit), weight, accumulate
#pragma unroll
        for (int j = 0; j < 4; j++) {
            float wgt = __fdividef(e[j], t[j]);
            float4 y0 = ld128_force(yp[j]);
            float4 y1 = ld128_force(yp[j] + 128);
            a0.x += wgt * y0.x; a0.y += wgt * y0.y;
            a0.z += wgt * y0.z; a0.w += wgt * y0.w;
            a1.x += wgt * y1.x; a1.y += wgt * y1.y;
            a1.z += wgt * y1.z; a1.w += wgt * y1.w;
        }
    }

    // self + aggregate, per-channel (8-lane group) L2 norm
    float v[8];
    v[0] = x0.x + a0.x; v[1] = x0.y + a0.y; v[2] = x0.z + a0.z; v[3] = x0.w + a0.w;
    v[4] = x1.x + a1.x; v[5] = x1.y + a1.y; v[6] = x1.z + a1.z; v[7] = x1.w + a1.w;
    float sq = 0.f;
#pragma unroll
    for (int k = 0; k < 8; k++) sq += v[k] * v[k];
    sq += __shfl_xor_sync(0xffffffffu, sq, 1);
    sq += __shfl_xor_sync(0xffffffffu, sq, 2);
    sq += __shfl_xor_sync(0xffffffffu, sq, 4);
    float sc = rsqrtf(fmaxf(sq, 1e-24f));
    if (pass == 2) {
        // canonical layout for d_out: lane's elements are [8l, 8l+8)
        float* drow = dst + (size_t)n * FDIM + lane * 8;
        *(float4*)drow       = make_float4(v[0] * sc, v[1] * sc, v[2] * sc, v[3] * sc);
        *(float4*)(drow + 4) = make_float4(v[4] * sc, v[5] * sc, v[6] * sc, v[7] * sc);
    } else {
        // permuted layout for g_feats
        float* drow = dst + (size_t)n * FDIM + lane * 4;
        *(float4*)drow         = make_float4(v[0] * sc, v[1] * sc, v[2] * sc, v[3] * sc);
        *(float4*)(drow + 128) = make_float4(v[4] * sc, v[5] * sc, v[6] * sc, v[7] * sc);
    }
}

// ============================================================
extern "C" void kernel_launch(void* const* d_in, const int* in_sizes, int n_in,
                              void* d_out, int out_size) {
    const float* features = (const float*)d_in[0];   // [6144, 512]
    const int*   adj      = (const int*)d_in[1];     // [6144, 6144]
    const float* W        = (const float*)d_in[2];   // [4, 512, 64]
    const float* b        = (const float*)d_in[3];   // [4, 1, 64]
    float* out = (float*)d_out;                      // [6144, 256]

    build_ell_kernel<<<NN / 8, 256>>>(adj);
    project_kernel<<<dim3(NN / 64, CHANNELS), 256>>>(features, W, b);
    iterate_kernel<<<NN / 4, 128>>>(0, out);
    iterate_kernel<<<NN / 4, 128>>>(1, out);
    iterate_kernel<<<NN / 4, 128>>>(2, out);
}

// round 15
// speedup vs baseline: 1.1422x; 1.1422x over previous
#include <cuda_runtime.h>
#include <cuda_bf16.h>
#include <cstdint>

#define NN 6144
#define IN_DIM 512
#define CHANNELS 4
#define C_DIM 64
#define FDIM 256          // CHANNELS * C_DIM
#define CAP 128           // max neighbors per row (mean ~31, sd ~5.5)

// -------- scratch (device globals; no allocation allowed) --------
// Rows of g_feats are stored PERMUTED: canonical element e (owner lane
// l = e>>3, sub s = e&7) lives at float offset (s>=4)*128 + l*4 + (s&3).
// Row NN is a permanent all-zero row (sentinel target).
__device__ float g_featsA[(size_t)(NN + 1) * FDIM];
__device__ float g_featsB[(size_t)(NN + 1) * FDIM];
__device__ int   g_ell[(size_t)NN * CAP + 64];
__device__ int   g_deg[NN];

// ============================================================
// Kernel 1: dense adj -> ELL (order-preserving, deterministic)
// warp/row, int4 + 4-ballot compaction, sentinel padding to x4.
// ============================================================
__global__ __launch_bounds__(256) void build_ell_kernel(const int* __restrict__ adj) {
    int row = blockIdx.x * 8 + (threadIdx.x >> 5);
    int lane = threadIdx.x & 31;
    const int4* arow = (const int4*)(adj + (size_t)row * NN);
    unsigned lt = (1u << lane) - 1u;
    int total = 0;
    int* erow = g_ell + (size_t)row * CAP;
    for (int it = 0; it < NN / 128; it++) {
        int4 v = arow[it * 32 + lane];
        bool p0 = v.x > 0, p1 = v.y > 0, p2 = v.z > 0, p3 = v.w > 0;
        unsigned b0 = __ballot_sync(0xffffffffu, p0);
        unsigned b1 = __ballot_sync(0xffffffffu, p1);
        unsigned b2 = __ballot_sync(0xffffffffu, p2);
        unsigned b3 = __ballot_sync(0xffffffffu, p3);
        int basec = __popc(b0 & lt) + __popc(b1 & lt) + __popc(b2 & lt) + __popc(b3 & lt);
        int idx0 = it * 128 + lane * 4;
        int pos = total + basec;
        if (p0) { if (pos < CAP) erow[pos] = idx0; pos++; }
        if (p1) { if (pos < CAP) erow[pos] = idx0 + 1; pos++; }
        if (p2) { if (pos < CAP) erow[pos] = idx0 + 2; pos++; }
        if (p3) { if (pos < CAP) erow[pos] = idx0 + 3; }
        total += __popc(b0) + __popc(b1) + __popc(b2) + __popc(b3);
    }
    int tc = total < CAP ? total : CAP;
    int pad = (tc + 3) & ~3;
    if (lane < pad - tc) erow[tc + lane] = NN;   // sentinel -> zero row
    if (lane == 0) g_deg[row] = pad;
}

// ============================================================
// Kernel 2: project via 3xTF32 tensor-core MMA (split precision).
// Block = 128 threads (4 warps), tile = 64 rows x 64 cols (one
// channel). Warp w owns rows [w*16, w*16+16) x all 64 cols
// (8 n-tiles of m16n8k8). A,B split hi/lo in smem; D += Ah*Bh +
// Ah*Bl + Al*Bh -> ~1e-6 relative error, deterministic.
// Epilogue: bias + per-row L2 norm (2 shfls) + permuted store.
// ============================================================
__device__ __forceinline__ uint32_t f2tf32(float x) {
    uint32_t r;
    asm("cvt.rna.tf32.f32 %0, %1;" : "=r"(r) : "f"(x));
    return r;
}

__global__ __launch_bounds__(128) void project_kernel(const float* __restrict__ feat,
                                                      const float* __restrict__ W,
                                                      const float* __restrict__ bias) {
    __shared__ float sAhi[64][40], sAlo[64][40];   // row-major, pad 40 (16B-aligned)
    __shared__ float sWhi[32][72], sWlo[32][72];   // [k][n], pad 72 (16B-aligned)

    const int c  = blockIdx.y;
    const int n0 = blockIdx.x * 64;
    const int t  = threadIdx.x;
    const int w  = t >> 5, lane = t & 31;
    const int g  = lane >> 2, tq = lane & 3;

    const float* Wc = W + (size_t)c * IN_DIM * C_DIM;

    float acc[8][4];
#pragma unroll
    for (int nt = 0; nt < 8; nt++)
#pragma unroll
        for (int k = 0; k < 4; k++) acc[nt][k] = 0.f;

    const int arow = t >> 1, aseg = t & 1;   // A loader: row, 16-float seg
    const int wk   = t >> 2, wseg = t & 3;   // W loader: k-row, 16-float seg
    const int r0 = w * 16 + g;               // warp-local row (0..63)

    for (int d0 = 0; d0 < IN_DIM; d0 += 32) {
        // ---- load + hi/lo split into smem ----
#pragma unroll
        for (int q = 0; q < 4; q++) {
            float4 v = *(const float4*)(feat + (size_t)(n0 + arow) * IN_DIM + d0 + aseg * 16 + q * 4);
            float hx = __uint_as_float(f2tf32(v.x));
            float hy = __uint_as_float(f2tf32(v.y));
            float hz = __uint_as_float(f2tf32(v.z));
            float hw = __uint_as_float(f2tf32(v.w));
            *(float4*)&sAhi[arow][aseg * 16 + q * 4] = make_float4(hx, hy, hz, hw);
            *(float4*)&sAlo[arow][aseg * 16 + q * 4] =
                make_float4(__uint_as_float(f2tf32(v.x - hx)), __uint_as_float(f2tf32(v.y - hy)),
                            __uint_as_float(f2tf32(v.z - hz)), __uint_as_float(f2tf32(v.w - hw)));
        }
#pragma unroll
        for (int q = 0; q < 4; q++) {
            float4 v = *(const float4*)(Wc + (size_t)(d0 + wk) * C_DIM + wseg * 16 + q * 4);
            float hx = __uint_as_float(f2tf32(v.x));
            float hy = __uint_as_float(f2tf32(v.y));
            float hz = __uint_as_float(f2tf32(v.z));
            float hw = __uint_as_float(f2tf32(v.w));
            *(float4*)&sWhi[wk][wseg * 16 + q * 4] = make_float4(hx, hy, hz, hw);
            *(float4*)&sWlo[wk][wseg * 16 + q * 4] =
                make_float4(__uint_as_float(f2tf32(v.x - hx)), __uint_as_float(f2tf32(v.y - hy)),
                            __uint_as_float(f2tf32(v.z - hz)), __uint_as_float(f2tf32(v.w - hw)));
        }
        __syncthreads();

        // ---- 4 k-steps of m16n8k8 per chunk ----
#pragma unroll
        for (int kk = 0; kk < 32; kk += 8) {
            uint32_t ah0 = __float_as_uint(sAhi[r0][kk + tq]);
            uint32_t ah1 = __float_as_uint(sAhi[r0 + 8][kk + tq]);
            uint32_t ah2 = __float_as_uint(sAhi[r0][kk + tq + 4]);
            uint32_t ah3 = __float_as_uint(sAhi[r0 + 8][kk + tq + 4]);
            uint32_t al0 = __float_as_uint(sAlo[r0][kk + tq]);
            uint32_t al1 = __float_as_uint(sAlo[r0 + 8][kk + tq]);
            uint32_t al2 = __float_as_uint(sAlo[r0][kk + tq + 4]);
            uint32_t al3 = __float_as_uint(sAlo[r0 + 8][kk + tq + 4]);
#pragma unroll
            for (int nt = 0; nt < 8; nt++) {
                int nc = nt * 8 + g;
                uint32_t bh0 = __float_as_uint(sWhi[kk + tq][nc]);
                uint32_t bh1 = __float_as_uint(sWhi[kk + tq + 4][nc]);
                uint32_t bl0 = __float_as_uint(sWlo[kk + tq][nc]);
                uint32_t bl1 = __float_as_uint(sWlo[kk + tq + 4][nc]);
#define MMA(A0,A1,A2,A3,B0,B1) \
    asm("mma.sync.aligned.m16n8k8.row.col.f32.tf32.tf32.f32 " \
        "{%0,%1,%2,%3}, {%4,%5,%6,%7}, {%8,%9}, {%0,%1,%2,%3};" \
        : "+f"(acc[nt][0]), "+f"(acc[nt][1]), "+f"(acc[nt][2]), "+f"(acc[nt][3]) \
        : "r"(A0), "r"(A1), "r"(A2), "r"(A3), "r"(B0), "r"(B1))
                MMA(ah0, ah1, ah2, ah3, bh0, bh1);   // hi*hi
                MMA(ah0, ah1, ah2, ah3, bl0, bl1);   // hi*lo
                MMA(al0, al1, al2, al3, bh0, bh1);   // lo*hi
#undef MMA
            }
        }
        __syncthreads();
    }

    // ---- epilogue: bias, per-row L2 norm, permuted store ----
    // lane holds rows {R0, R0+8}, cols nt*8 + 2tq, +1
    float sos0 = 0.f, sos1 = 0.f;
#pragma unroll
    for (int nt = 0; nt < 8; nt++) {
        float2 bb = *(const float2*)(bias + c * C_DIM + nt * 8 + 2 * tq);
        acc[nt][0] += bb.x; acc[nt][1] += bb.y;
        acc[nt][2] += bb.x; acc[nt][3] += bb.y;
        sos0 += acc[nt][0] * acc[nt][0] + acc[nt][1] * acc[nt][1];
        sos1 += acc[nt][2] * acc[nt][2] + acc[nt][3] * acc[nt][3];
    }
    sos0 += __shfl_xor_sync(0xffffffffu, sos0, 1);
    sos0 += __shfl_xor_sync(0xffffffffu, sos0, 2);
    sos1 += __shfl_xor_sync(0xffffffffu, sos1, 1);
    sos1 += __shfl_xor_sync(0xffffffffu, sos1, 2);
    float sc0 = rsqrtf(fmaxf(sos0, 1e-24f));
    float sc1 = rsqrtf(fmaxf(sos1, 1e-24f));

    const int R0 = n0 + w * 16 + g;
    const int R1 = R0 + 8;
    // permuted offset for canonical s = 2tq + b: (s>=4)*128 + l*4 + (s&3)
    const int off = (tq >= 2 ? 128 : 0) + ((2 * tq) & 3);
#pragma unroll
    for (int nt = 0; nt < 8; nt++) {
        int pp = (c * 8 + nt) * 4 + off;
        *(float2*)(g_featsA + (size_t)R0 * FDIM + pp) =
            make_float2(acc[nt][0] * sc0, acc[nt][1] * sc0);
        *(float2*)(g_featsA + (size_t)R1 * FDIM + pp) =
            make_float2(acc[nt][2] * sc1, acc[nt][3] * sc1);
    }
}

// ============================================================
// Kernel 3: one iteration (R13 version verbatim: warp/node,
// permuted layout, 4-way ILP, 5 shfls/edge, regs ~72).
// ============================================================
__global__ __launch_bounds__(128) void iterate_kernel(int pass, float* __restrict__ d_final) {
    const float* __restrict__ src = (pass == 1) ? g_featsB : g_featsA;
    float* __restrict__ dst = (pass == 0) ? g_featsB : (pass == 1) ? g_featsA : d_final;

    const int w = threadIdx.x >> 5, lane = threadIdx.x & 31;
    const int n = blockIdx.x * 4 + w;

    const float* xrow = src + (size_t)n * FDIM + lane * 4;
    float4 x0 = *(const float4*)xrow;          // canonical [8l, 8l+4)
    float4 x1 = *(const float4*)(xrow + 128);  // canonical [8l+4, 8l+8)
    float4 a0 = make_float4(0.f, 0.f, 0.f, 0.f);
    float4 a1 = make_float4(0.f, 0.f, 0.f, 0.f);

    const int dp = g_deg[n];                 // padded to multiple of 4
    const int* erow = g_ell + (size_t)n * CAP;

    for (int i = 0; i < dp; i += 4) {
        int col[4];
#pragma unroll
        for (int j = 0; j < 4; j++) col[j] = __ldg(erow + i + j);   // uniform

        float4 y0[4], y1[4];
#pragma unroll
        for (int j = 0; j < 4; j++) {
            const float* yr = src + (size_t)col[j] * FDIM + lane * 4;
            y0[j] = *(const float4*)yr;          // dense 512B across warp
            y1[j] = *(const float4*)(yr + 128);  // dense 512B across warp
        }

        float p[4];
#pragma unroll
        for (int j = 0; j < 4; j++)
            p[j] = x0.x * y0[j].x + x0.y * y0[j].y + x0.z * y0[j].z + x0.w * y0[j].w +
                   x1.x * y1[j].x + x1.y * y1[j].y + x1.z * y1[j].z + x1.w * y1[j].w;
#pragma unroll
        for (int j = 0; j < 4; j++) p[j] += __shfl_xor_sync(0xffffffffu, p[j], 1);
#pragma unroll
        for (int j = 0; j < 4; j++) p[j] += __shfl_xor_sync(0xffffffffu, p[j], 2);
#pragma unroll
        for (int j = 0; j < 4; j++) p[j] += __shfl_xor_sync(0xffffffffu, p[j], 4);
        // |p| <= 1 (unit-norm channel rows): no max-shift needed
        float e[4], t[4];
#pragma unroll
        for (int j = 0; j < 4; j++) e[j] = __expf(p[j]);
#pragma unroll
        for (int j = 0; j < 4; j++) t[j] = e[j] + __shfl_xor_sync(0xffffffffu, e[j], 8);
#pragma unroll
        for (int j = 0; j < 4; j++) t[j] += __shfl_xor_sync(0xffffffffu, t[j], 16);
#pragma unroll
        for (int j = 0; j < 4; j++) {
            float wgt = __fdividef(e[j], t[j]);
            a0.x += wgt * y0[j].x; a0.y += wgt * y0[j].y;
            a0.z += wgt * y0[j].z; a0.w += wgt * y0[j].w;
            a1.x += wgt * y1[j].x; a1.y += wgt * y1[j].y;
            a1.z += wgt * y1[j].z; a1.w += wgt * y1[j].w;
        }
    }

    // self + aggregate, per-channel (8-lane group) L2 norm
    float v[8];
    v[0] = x0.x + a0.x; v[1] = x0.y + a0.y; v[2] = x0.z + a0.z; v[3] = x0.w + a0.w;
    v[4] = x1.x + a1.x; v[5] = x1.y + a1.y; v[6] = x1.z + a1.z; v[7] = x1.w + a1.w;
    float sq = 0.f;
#pragma unroll
    for (int k = 0; k < 8; k++) sq += v[k] * v[k];
    sq += __shfl_xor_sync(0xffffffffu, sq, 1);
    sq += __shfl_xor_sync(0xffffffffu, sq, 2);
    sq += __shfl_xor_sync(0xffffffffu, sq, 4);
    float sc = rsqrtf(fmaxf(sq, 1e-24f));
    if (pass == 2) {
        // canonical layout for d_out: lane's elements are [8l, 8l+8)
        float* drow = dst + (size_t)n * FDIM + lane * 8;
        *(float4*)drow       = make_float4(v[0] * sc, v[1] * sc, v[2] * sc, v[3] * sc);
        *(float4*)(drow + 4) = make_float4(v[4] * sc, v[5] * sc, v[6] * sc, v[7] * sc);
    } else {
        // permuted layout for g_feats
        float* drow = dst + (size_t)n * FDIM + lane * 4;
        *(float4*)drow         = make_float4(v[0] * sc, v[1] * sc, v[2] * sc, v[3] * sc);
        *(float4*)(drow + 128) = make_float4(v[4] * sc, v[5] * sc, v[6] * sc, v[7] * sc);
    }
}

// ============================================================
extern "C" void kernel_launch(void* const* d_in, const int* in_sizes, int n_in,
                              void* d_out, int out_size) {
    const float* features = (const float*)d_in[0];   // [6144, 512]
    const int*   adj      = (const int*)d_in[1];     // [6144, 6144]
    const float* W        = (const float*)d_in[2];   // [4, 512, 64]
    const float* b        = (const float*)d_in[3];   // [4, 1, 64]
    float* out = (float*)d_out;                      // [6144, 256]

    build_ell_kernel<<<NN / 8, 256>>>(adj);
    project_kernel<<<dim3(NN / 64, CHANNELS), 128>>>(features, W, b);
    iterate_kernel<<<NN / 4, 128>>>(0, out);
    iterate_kernel<<<NN / 4, 128>>>(1, out);
    iterate_kernel<<<NN / 4, 128>>>(2, out);
}

// round 16
// speedup vs baseline: 1.3114x; 1.1481x over previous
#include <cuda_runtime.h>
#include <cuda_bf16.h>
#include <cstdint>

#define NN 6144
#define IN_DIM 512
#define CHANNELS 4
#define C_DIM 64
#define FDIM 256          // CHANNELS * C_DIM
#define CAP 128           // max neighbors per row (mean ~31, sd ~5.5)

// -------- scratch (device globals; no allocation allowed) --------
// Rows of g_feats are stored PERMUTED: canonical element e (owner lane
// l = e>>3, sub s = e&7) lives at float offset (s>=4)*128 + l*4 + (s&3).
// Row NN is a permanent all-zero row (sentinel target).
__device__ float g_featsA[(size_t)(NN + 1) * FDIM];
__device__ float g_featsB[(size_t)(NN + 1) * FDIM];
__device__ int   g_ell[(size_t)NN * CAP + 64];
__device__ int   g_deg[NN];

// ============================================================
// Kernel 1: dense adj -> ELL (order-preserving, deterministic)
// warp/row, int4 + 4-ballot compaction, sentinel padding to x4.
// ============================================================
__global__ __launch_bounds__(256) void build_ell_kernel(const int* __restrict__ adj) {
    int row = blockIdx.x * 8 + (threadIdx.x >> 5);
    int lane = threadIdx.x & 31;
    const int4* arow = (const int4*)(adj + (size_t)row * NN);
    unsigned lt = (1u << lane) - 1u;
    int total = 0;
    int* erow = g_ell + (size_t)row * CAP;
    for (int it = 0; it < NN / 128; it++) {
        int4 v = arow[it * 32 + lane];
        bool p0 = v.x > 0, p1 = v.y > 0, p2 = v.z > 0, p3 = v.w > 0;
        unsigned b0 = __ballot_sync(0xffffffffu, p0);
        unsigned b1 = __ballot_sync(0xffffffffu, p1);
        unsigned b2 = __ballot_sync(0xffffffffu, p2);
        unsigned b3 = __ballot_sync(0xffffffffu, p3);
        int basec = __popc(b0 & lt) + __popc(b1 & lt) + __popc(b2 & lt) + __popc(b3 & lt);
        int idx0 = it * 128 + lane * 4;
        int pos = total + basec;
        if (p0) { if (pos < CAP) erow[pos] = idx0; pos++; }
        if (p1) { if (pos < CAP) erow[pos] = idx0 + 1; pos++; }
        if (p2) { if (pos < CAP) erow[pos] = idx0 + 2; pos++; }
        if (p3) { if (pos < CAP) erow[pos] = idx0 + 3; }
        total += __popc(b0) + __popc(b1) + __popc(b2) + __popc(b3);
    }
    int tc = total < CAP ? total : CAP;
    int pad = (tc + 3) & ~3;
    if (lane < pad - tc) erow[tc + lane] = NN;   // sentinel -> zero row
    if (lane == 0) g_deg[row] = pad;
}

// ============================================================
// Kernel 2: project via bf16 3-term split MMA (m16n8k16).
// Tile 32 rows x 64 cols, 128 threads (4 warps): warp w handles
// rows (w&1)*16..+16, cols (w>>1)*32..+32 (4 n-tiles). A,W split
// hi/lo bf16 pairs in smem; D += Ah*Wh + Ah*Wl + Al*Wh.
// rel err ~2^-18 per product -> ~1e-5 end to end. Deterministic.
// ============================================================
__device__ __forceinline__ uint32_t bfpair(float lo, float hi) {
    uint32_t r;
    asm("cvt.rn.bf16x2.f32 %0, %1, %2;" : "=r"(r) : "f"(hi), "f"(lo));
    return r;
}
__device__ __forceinline__ void split_pair(float e, float o, uint32_t& h, uint32_t& l) {
    h = bfpair(e, o);                               // low = bf16(e), high = bf16(o)
    float he = __uint_as_float(h << 16);
    float ho = __uint_as_float(h & 0xffff0000u);
    l = bfpair(e - he, o - ho);
}

#define BMMA(C, A0, A1, A2, A3, B0, B1) \
    asm("mma.sync.aligned.m16n8k16.row.col.f32.bf16.bf16.f32 " \
        "{%0,%1,%2,%3}, {%4,%5,%6,%7}, {%8,%9}, {%0,%1,%2,%3};" \
        : "+f"(C[0]), "+f"(C[1]), "+f"(C[2]), "+f"(C[3]) \
        : "r"(A0), "r"(A1), "r"(A2), "r"(A3), "r"(B0), "r"(B1))

__global__ __launch_bounds__(128) void project_kernel(const float* __restrict__ feat,
                                                      const float* __restrict__ W,
                                                      const float* __restrict__ bias) {
    __shared__ uint32_t sAh[32][20], sAl[32][20];   // [row][k-pair], pad 20: conflict-free frags
    __shared__ uint32_t sWh[16][72], sWl[16][72];   // [k-pair-row][n], pad 72: conflict-free frags
    __shared__ float spart[2][32];                  // per-row sum-of-squares partials by col-half

    const int c  = blockIdx.y;
    const int n0 = blockIdx.x * 32;
    const int t  = threadIdx.x;
    const int w  = t >> 5, lane = t & 31;
    const int g  = lane >> 2, tq = lane & 3;
    const int rhalf = w & 1, chalf = w >> 1;
    const int r0 = rhalf * 16 + g;                  // tile-local row (plus +8 pair)

    const float* Wc = W + (size_t)c * IN_DIM * C_DIM;

    float acc[4][4];
#pragma unroll
    for (int nt = 0; nt < 4; nt++)
#pragma unroll
        for (int k = 0; k < 4; k++) acc[nt][k] = 0.f;

    const int arow = t >> 2, aseg = t & 3;          // A stage: row, k-quarter (8 floats)
    const int kp   = t >> 3, m = t & 7;             // W stage: k-pair-row, col-octet

    for (int d0 = 0; d0 < IN_DIM; d0 += 32) {
        // ---- stage A: 32 rows x 32 k, split to bf16 hi/lo pairs ----
        {
            const float* fp = feat + (size_t)(n0 + arow) * IN_DIM + d0 + aseg * 8;
            float4 v0 = *(const float4*)fp;
            float4 v1 = *(const float4*)(fp + 4);
            uint32_t h0, h1, h2, h3, l0, l1, l2, l3;
            split_pair(v0.x, v0.y, h0, l0);
            split_pair(v0.z, v0.w, h1, l1);
            split_pair(v1.x, v1.y, h2, l2);
            split_pair(v1.z, v1.w, h3, l3);
            *(uint4*)&sAh[arow][aseg * 4] = make_uint4(h0, h1, h2, h3);
            *(uint4*)&sAl[arow][aseg * 4] = make_uint4(l0, l1, l2, l3);
        }
        // ---- stage W: 32 k x 64 n, pairs across adjacent k rows ----
        {
            const float* wp = Wc + (size_t)(d0 + 2 * kp) * C_DIM + m * 8;
            float4 e0 = *(const float4*)wp;
            float4 e1 = *(const float4*)(wp + 4);
            float4 o0 = *(const float4*)(wp + 64);
            float4 o1 = *(const float4*)(wp + 68);
            uint32_t wh[8], wl[8];
            split_pair(e0.x, o0.x, wh[0], wl[0]);
            split_pair(e0.y, o0.y, wh[1], wl[1]);
            split_pair(e0.z, o0.z, wh[2], wl[2]);
            split_pair(e0.w, o0.w, wh[3], wl[3]);
            split_pair(e1.x, o1.x, wh[4], wl[4]);
            split_pair(e1.y, o1.y, wh[5], wl[5]);
            split_pair(e1.z, o1.z, wh[6], wl[6]);
            split_pair(e1.w, o1.w, wh[7], wl[7]);
            *(uint4*)&sWh[kp][m * 8]     = make_uint4(wh[0], wh[1], wh[2], wh[3]);
            *(uint4*)&sWh[kp][m * 8 + 4] = make_uint4(wh[4], wh[5], wh[6], wh[7]);
            *(uint4*)&sWl[kp][m * 8]     = make_uint4(wl[0], wl[1], wl[2], wl[3]);
            *(uint4*)&sWl[kp][m * 8 + 4] = make_uint4(wl[4], wl[5], wl[6], wl[7]);
        }
        __syncthreads();

        // ---- 2 k16-steps per chunk ----
#pragma unroll
        for (int s = 0; s < 2; s++) {
            const int kb = s * 8;
            uint32_t ah0 = sAh[r0][kb + tq];
            uint32_t ah1 = sAh[r0 + 8][kb + tq];
            uint32_t ah2 = sAh[r0][kb + tq + 4];
            uint32_t ah3 = sAh[r0 + 8][kb + tq + 4];
            uint32_t al0 = sAl[r0][kb + tq];
            uint32_t al1 = sAl[r0 + 8][kb + tq];
            uint32_t al2 = sAl[r0][kb + tq + 4];
            uint32_t al3 = sAl[r0 + 8][kb + tq + 4];
#pragma unroll
            for (int nt = 0; nt < 4; nt++) {
                const int nc = chalf * 32 + nt * 8 + g;
                uint32_t bh0 = sWh[kb + tq][nc];
                uint32_t bh1 = sWh[kb + tq + 4][nc];
                uint32_t bl0 = sWl[kb + tq][nc];
                uint32_t bl1 = sWl[kb + tq + 4][nc];
                BMMA(acc[nt], ah0, ah1, ah2, ah3, bh0, bh1);
                BMMA(acc[nt], ah0, ah1, ah2, ah3, bl0, bl1);
                BMMA(acc[nt], al0, al1, al2, al3, bh0, bh1);
            }
        }
        __syncthreads();
    }

    // ---- epilogue: bias, cross-warp per-row L2 norm, permuted store ----
    float sos0 = 0.f, sos1 = 0.f;
#pragma unroll
    for (int nt = 0; nt < 4; nt++) {
        float2 bb = *(const float2*)(bias + c * C_DIM + chalf * 32 + nt * 8 + 2 * tq);
        acc[nt][0] += bb.x; acc[nt][1] += bb.y;
        acc[nt][2] += bb.x; acc[nt][3] += bb.y;
        sos0 += acc[nt][0] * acc[nt][0] + acc[nt][1] * acc[nt][1];
        sos1 += acc[nt][2] * acc[nt][2] + acc[nt][3] * acc[nt][3];
    }
    sos0 += __shfl_xor_sync(0xffffffffu, sos0, 1);
    sos0 += __shfl_xor_sync(0xffffffffu, sos0, 2);
    sos1 += __shfl_xor_sync(0xffffffffu, sos1, 1);
    sos1 += __shfl_xor_sync(0xffffffffu, sos1, 2);
    if (tq == 0) {
        spart[chalf][r0] = sos0;
        spart[chalf][r0 + 8] = sos1;
    }
    __syncthreads();
    float sc0 = rsqrtf(fmaxf(spart[0][r0] + spart[1][r0], 1e-24f));
    float sc1 = rsqrtf(fmaxf(spart[0][r0 + 8] + spart[1][r0 + 8], 1e-24f));

    // permuted position: canonical col cc = chalf*32 + nt*8 + 2tq (+1)
    // owner lane l = c*8 + chalf*4 + nt, sub s = 2tq (+1)
    const int off = (tq >= 2 ? 128 : 0) + ((2 * tq) & 3);
#pragma unroll
    for (int nt = 0; nt < 4; nt++) {
        int pp = (c * 8 + chalf * 4 + nt) * 4 + off;
        *(float2*)(g_featsA + (size_t)(n0 + r0) * FDIM + pp) =
            make_float2(acc[nt][0] * sc0, acc[nt][1] * sc0);
        *(float2*)(g_featsA + (size_t)(n0 + r0 + 8) * FDIM + pp) =
            make_float2(acc[nt][2] * sc1, acc[nt][3] * sc1);
    }
}

// ============================================================
// Kernel 3: one iteration (R13 version verbatim: warp/node,
// permuted layout, 4-way ILP, 5 shfls/edge, regs ~72).
// ============================================================
__global__ __launch_bounds__(128) void iterate_kernel(int pass, float* __restrict__ d_final) {
    const float* __restrict__ src = (pass == 1) ? g_featsB : g_featsA;
    float* __restrict__ dst = (pass == 0) ? g_featsB : (pass == 1) ? g_featsA : d_final;

    const int w = threadIdx.x >> 5, lane = threadIdx.x & 31;
    const int n = blockIdx.x * 4 + w;

    const float* xrow = src + (size_t)n * FDIM + lane * 4;
    float4 x0 = *(const float4*)xrow;          // canonical [8l, 8l+4)
    float4 x1 = *(const float4*)(xrow + 128);  // canonical [8l+4, 8l+8)
    float4 a0 = make_float4(0.f, 0.f, 0.f, 0.f);
    float4 a1 = make_float4(0.f, 0.f, 0.f, 0.f);

    const int dp = g_deg[n];                 // padded to multiple of 4
    const int* erow = g_ell + (size_t)n * CAP;

    for (int i = 0; i < dp; i += 4) {
        int col[4];
#pragma unroll
        for (int j = 0; j < 4; j++) col[j] = __ldg(erow + i + j);   // uniform

        float4 y0[4], y1[4];
#pragma unroll
        for (int j = 0; j < 4; j++) {
            const float* yr = src + (size_t)col[j] * FDIM + lane * 4;
            y0[j] = *(const float4*)yr;          // dense 512B across warp
            y1[j] = *(const float4*)(yr + 128);  // dense 512B across warp
        }

        float p[4];
#pragma unroll
        for (int j = 0; j < 4; j++)
            p[j] = x0.x * y0[j].x + x0.y * y0[j].y + x0.z * y0[j].z + x0.w * y0[j].w +
                   x1.x * y1[j].x + x1.y * y1[j].y + x1.z * y1[j].z + x1.w * y1[j].w;
#pragma unroll
        for (int j = 0; j < 4; j++) p[j] += __shfl_xor_sync(0xffffffffu, p[j], 1);
#pragma unroll
        for (int j = 0; j < 4; j++) p[j] += __shfl_xor_sync(0xffffffffu, p[j], 2);
#pragma unroll
        for (int j = 0; j < 4; j++) p[j] += __shfl_xor_sync(0xffffffffu, p[j], 4);
        // |p| <= 1 (unit-norm channel rows): no max-shift needed
        float e[4], t[4];
#pragma unroll
        for (int j = 0; j < 4; j++) e[j] = __expf(p[j]);
#pragma unroll
        for (int j = 0; j < 4; j++) t[j] = e[j] + __shfl_xor_sync(0xffffffffu, e[j], 8);
#pragma unroll
        for (int j = 0; j < 4; j++) t[j] += __shfl_xor_sync(0xffffffffu, t[j], 16);
#pragma unroll
        for (int j = 0; j < 4; j++) {
            float wgt = __fdividef(e[j], t[j]);
            a0.x += wgt * y0[j].x; a0.y += wgt * y0[j].y;
            a0.z += wgt * y0[j].z; a0.w += wgt * y0[j].w;
            a1.x += wgt * y1[j].x; a1.y += wgt * y1[j].y;
            a1.z += wgt * y1[j].z; a1.w += wgt * y1[j].w;
        }
    }

    // self + aggregate, per-channel (8-lane group) L2 norm
    float v[8];
    v[0] = x0.x + a0.x; v[1] = x0.y + a0.y; v[2] = x0.z + a0.z; v[3] = x0.w + a0.w;
    v[4] = x1.x + a1.x; v[5] = x1.y + a1.y; v[6] = x1.z + a1.z; v[7] = x1.w + a1.w;
    float sq = 0.f;
#pragma unroll
    for (int k = 0; k < 8; k++) sq += v[k] * v[k];
    sq += __shfl_xor_sync(0xffffffffu, sq, 1);
    sq += __shfl_xor_sync(0xffffffffu, sq, 2);
    sq += __shfl_xor_sync(0xffffffffu, sq, 4);
    float sc = rsqrtf(fmaxf(sq, 1e-24f));
    if (pass == 2) {
        // canonical layout for d_out: lane's elements are [8l, 8l+8)
        float* drow = dst + (size_t)n * FDIM + lane * 8;
        *(float4*)drow       = make_float4(v[0] * sc, v[1] * sc, v[2] * sc, v[3] * sc);
        *(float4*)(drow + 4) = make_float4(v[4] * sc, v[5] * sc, v[6] * sc, v[7] * sc);
    } else {
        // permuted layout for g_feats
        float* drow = dst + (size_t)n * FDIM + lane * 4;
        *(float4*)drow         = make_float4(v[0] * sc, v[1] * sc, v[2] * sc, v[3] * sc);
        *(float4*)(drow + 128) = make_float4(v[4] * sc, v[5] * sc, v[6] * sc, v[7] * sc);
    }
}

// ============================================================
extern "C" void kernel_launch(void* const* d_in, const int* in_sizes, int n_in,
                              void* d_out, int out_size) {
    const float* features = (const float*)d_in[0];   // [6144, 512]
    const int*   adj      = (const int*)d_in[1];     // [6144, 6144]
    const float* W        = (const float*)d_in[2];   // [4, 512, 64]
    const float* b        = (const float*)d_in[3];   // [4, 1, 64]
    float* out = (float*)d_out;                      // [6144, 256]

    build_ell_kernel<<<NN / 8, 256>>>(adj);
    project_kernel<<<dim3(NN / 32, CHANNELS), 128>>>(features, W, b);
    iterate_kernel<<<NN / 4, 128>>>(0, out);
    iterate_kernel<<<NN / 4, 128>>>(1, out);
    iterate_kernel<<<NN / 4, 128>>>(2, out);
}